// round 1
// baseline (speedup 1.0000x reference)
#include <cuda_runtime.h>
#include <math.h>

// Problem constants (fixed by the dataset)
#define BB   4
#define N1   4096
#define N2   16384
#define DIM1 512
#define DIM2 256
#define DOUT 256

// Scratch (no allocation allowed -> __device__ globals)
__device__ float g_feats1[BB * N1 * DOUT];          // 16.8 MB
__device__ int   g_idx[BB * N2 * 3];
__device__ float g_w[BB * N2 * 3];

// ---------------------------------------------------------------------------
// Fused GEMM + BatchNorm(eval) + ReLU
//   C[m,n] = relu( (sum_k A[m,k] * W[n,k]) * scale[n] + shift[n] )
// scale = gamma / sqrt(var+eps), shift = (bias - mean)*scale + beta
// Tiling: BM=128, BN=64, BK=16, 256 threads, 8x4 micro-tile per thread.
// M divisible by 128, K divisible by 16, N = 256 (4 column tiles). No guards.
// ---------------------------------------------------------------------------
__global__ __launch_bounds__(256)
void gemm_bn_relu_kernel(const float* __restrict__ A,   // [M,K]
                         const float* __restrict__ W,   // [DOUT,K]
                         const float* __restrict__ bias,
                         const float* __restrict__ gamma,
                         const float* __restrict__ beta,
                         const float* __restrict__ mean,
                         const float* __restrict__ var,
                         float* __restrict__ C,         // [M,DOUT]
                         int M, int K)
{
    const int BM = 128, BN = 64, BK = 16;
    __shared__ float As[BK][BM];
    __shared__ float Bs[BK][BN];

    const int tid = threadIdx.x;
    const int m0  = blockIdx.y * BM;
    const int n0  = blockIdx.x * BN;
    const int tm  = tid >> 4;   // 0..15 -> row group (8 rows)
    const int tn  = tid & 15;   // 0..15 -> col group (4 cols)

    float acc[8][4];
#pragma unroll
    for (int i = 0; i < 8; i++)
#pragma unroll
        for (int j = 0; j < 4; j++) acc[i][j] = 0.f;

    for (int k0 = 0; k0 < K; k0 += BK) {
        // Load A tile: 128x16 floats = 512 float4, coalesced (8 rows per warp)
#pragma unroll
        for (int i = 0; i < 2; i++) {
            int id = i * 256 + tid;
            int r  = id >> 2;           // 0..127
            int c  = (id & 3) * 4;      // 0,4,8,12
            float4 v = *reinterpret_cast<const float4*>(
                &A[(size_t)(m0 + r) * K + k0 + c]);
            As[c + 0][r] = v.x; As[c + 1][r] = v.y;
            As[c + 2][r] = v.z; As[c + 3][r] = v.w;
        }
        // Load B tile: 64x16 floats = 256 float4
        {
            int r = tid >> 2;           // 0..63
            int c = (tid & 3) * 4;
            float4 v = *reinterpret_cast<const float4*>(
                &W[(size_t)(n0 + r) * K + k0 + c]);
            Bs[c + 0][r] = v.x; Bs[c + 1][r] = v.y;
            Bs[c + 2][r] = v.z; Bs[c + 3][r] = v.w;
        }
        __syncthreads();

#pragma unroll
        for (int kk = 0; kk < BK; kk++) {
            float a[8], b4[4];
            float4 a0 = *reinterpret_cast<const float4*>(&As[kk][tm * 8]);
            float4 a1 = *reinterpret_cast<const float4*>(&As[kk][tm * 8 + 4]);
            a[0]=a0.x; a[1]=a0.y; a[2]=a0.z; a[3]=a0.w;
            a[4]=a1.x; a[5]=a1.y; a[6]=a1.z; a[7]=a1.w;
            float4 bv = *reinterpret_cast<const float4*>(&Bs[kk][tn * 4]);
            b4[0]=bv.x; b4[1]=bv.y; b4[2]=bv.z; b4[3]=bv.w;
#pragma unroll
            for (int i = 0; i < 8; i++)
#pragma unroll
                for (int j = 0; j < 4; j++)
                    acc[i][j] = fmaf(a[i], b4[j], acc[i][j]);
        }
        __syncthreads();
    }

    // Epilogue: BN + ReLU
    float sc[4], sh[4];
#pragma unroll
    for (int j = 0; j < 4; j++) {
        int n = n0 + tn * 4 + j;
        float s = gamma[n] * rsqrtf(var[n] + 1e-5f);
        sc[j] = s;
        sh[j] = (bias[n] - mean[n]) * s + beta[n];
    }
#pragma unroll
    for (int i = 0; i < 8; i++) {
        int m = m0 + tm * 8 + i;
        float4 o;
        o.x = fmaxf(fmaf(acc[i][0], sc[0], sh[0]), 0.f);
        o.y = fmaxf(fmaf(acc[i][1], sc[1], sh[1]), 0.f);
        o.z = fmaxf(fmaf(acc[i][2], sc[2], sh[2]), 0.f);
        o.w = fmaxf(fmaf(acc[i][3], sc[3], sh[3]), 0.f);
        *reinterpret_cast<float4*>(&C[(size_t)m * DOUT + n0 + tn * 4]) = o;
    }
}

// ---------------------------------------------------------------------------
// 3-NN search: for each target point (xyz2) find 3 nearest source points
// (xyz1) per batch, output global feats1 row indices + normalized inverse-
// distance weights. Source cloud (4096x3 = 48KB) staged in shared memory.
// ---------------------------------------------------------------------------
__global__ __launch_bounds__(256)
void knn3_kernel(const float* __restrict__ xyz_tgt,  // [BB,N2,3]
                 const float* __restrict__ xyz_src,  // [BB,N1,3]
                 int* __restrict__ idx,              // [BB*N2,3]
                 float* __restrict__ w)              // [BB*N2,3]
{
    __shared__ float sx[N1];
    __shared__ float sy[N1];
    __shared__ float sz[N1];

    const int b = blockIdx.y;
    const int t = blockIdx.x * 256 + threadIdx.x;    // target idx within batch

    const float* src = xyz_src + (size_t)b * N1 * 3;
    for (int i = threadIdx.x; i < N1; i += 256) {
        sx[i] = src[3 * i + 0];
        sy[i] = src[3 * i + 1];
        sz[i] = src[3 * i + 2];
    }
    __syncthreads();

    const float* tp = xyz_tgt + ((size_t)b * N2 + t) * 3;
    const float tx = tp[0], ty = tp[1], tz = tp[2];

    float d0 = 3.4e38f, d1 = 3.4e38f, d2 = 3.4e38f;
    int   i0 = 0,       i1 = 0,       i2 = 0;

#pragma unroll 4
    for (int s = 0; s < N1; s++) {
        float dx = sx[s] - tx;
        float dy = sy[s] - ty;
        float dz = sz[s] - tz;
        float d  = fmaf(dx, dx, fmaf(dy, dy, dz * dz));
        if (d < d2) {
            if (d < d1) {
                d2 = d1; i2 = i1;
                if (d < d0) { d1 = d0; i1 = i0; d0 = d; i0 = s; }
                else        { d1 = d;  i1 = s; }
            } else {
                d2 = d; i2 = s;
            }
        }
    }

    float w0 = 1.f / (d0 + 1e-8f);
    float w1 = 1.f / (d1 + 1e-8f);
    float w2 = 1.f / (d2 + 1e-8f);
    float inv = 1.f / (w0 + w1 + w2);

    size_t o = ((size_t)b * N2 + t) * 3;
    idx[o + 0] = b * N1 + i0;   // global feats1 row
    idx[o + 1] = b * N1 + i1;
    idx[o + 2] = b * N1 + i2;
    w[o + 0] = w0 * inv;
    w[o + 1] = w1 * inv;
    w[o + 2] = w2 * inv;
}

// ---------------------------------------------------------------------------
// out[r,:] += sum_k w[r,k] * feats1[idx[r,k], :]   (out already holds feats2)
// One block of 256 threads covers 4 rows; each thread does one float4 (4 ch).
// ---------------------------------------------------------------------------
__global__ __launch_bounds__(256)
void interp_add_kernel(const float* __restrict__ feats1,
                       const int* __restrict__ idx,
                       const float* __restrict__ w,
                       float* __restrict__ out)
{
    const int r  = blockIdx.x * 4 + (threadIdx.x >> 6);   // row 0..65535
    const int c4 = (threadIdx.x & 63) * 4;                // channel group

    const int   j0 = idx[r * 3 + 0];
    const int   j1 = idx[r * 3 + 1];
    const int   j2 = idx[r * 3 + 2];
    const float w0 = w[r * 3 + 0];
    const float w1 = w[r * 3 + 1];
    const float w2 = w[r * 3 + 2];

    const float4 f0 = *reinterpret_cast<const float4*>(&feats1[(size_t)j0 * DOUT + c4]);
    const float4 f1 = *reinterpret_cast<const float4*>(&feats1[(size_t)j1 * DOUT + c4]);
    const float4 f2 = *reinterpret_cast<const float4*>(&feats1[(size_t)j2 * DOUT + c4]);

    float4 o = *reinterpret_cast<float4*>(&out[(size_t)r * DOUT + c4]);
    o.x += w0 * f0.x + w1 * f1.x + w2 * f2.x;
    o.y += w0 * f0.y + w1 * f1.y + w2 * f2.y;
    o.z += w0 * f0.z + w1 * f1.z + w2 * f2.z;
    o.w += w0 * f0.w + w1 * f1.w + w2 * f2.w;
    *reinterpret_cast<float4*>(&out[(size_t)r * DOUT + c4]) = o;
}

// ---------------------------------------------------------------------------
extern "C" void kernel_launch(void* const* d_in, const int* in_sizes, int n_in,
                              void* d_out, int out_size)
{
    const float* xyz1    = (const float*)d_in[0];
    const float* points1 = (const float*)d_in[1];
    const float* xyz2    = (const float*)d_in[2];
    const float* points2 = (const float*)d_in[3];
    const float* W1 = (const float*)d_in[4];
    const float* b1 = (const float*)d_in[5];
    const float* g1 = (const float*)d_in[6];
    const float* be1= (const float*)d_in[7];
    const float* m1 = (const float*)d_in[8];
    const float* v1 = (const float*)d_in[9];
    const float* W2 = (const float*)d_in[10];
    const float* b2 = (const float*)d_in[11];
    const float* g2 = (const float*)d_in[12];
    const float* be2= (const float*)d_in[13];
    const float* m2 = (const float*)d_in[14];
    const float* v2 = (const float*)d_in[15];
    float* out = (float*)d_out;

    float* feats1_ptr = nullptr;
    int*   idx_ptr    = nullptr;
    float* w_ptr      = nullptr;
    cudaGetSymbolAddress((void**)&feats1_ptr, g_feats1);
    cudaGetSymbolAddress((void**)&idx_ptr,    g_idx);
    cudaGetSymbolAddress((void**)&w_ptr,      g_w);

    // KNN (independent of GEMMs)
    knn3_kernel<<<dim3(N2 / 256, BB), 256>>>(xyz2, xyz1, idx_ptr, w_ptr);

    // feats1 = relu(BN(points1 @ W1^T + b1))  -> scratch
    gemm_bn_relu_kernel<<<dim3(DOUT / 64, (BB * N1) / 128), 256>>>(
        points1, W1, b1, g1, be1, m1, v1, feats1_ptr, BB * N1, DIM1);

    // feats2 = relu(BN(points2 @ W2^T + b2))  -> d_out
    gemm_bn_relu_kernel<<<dim3(DOUT / 64, (BB * N2) / 128), 256>>>(
        points2, W2, b2, g2, be2, m2, v2, out, BB * N2, DIM2);

    // out += 3-NN weighted interpolation of feats1
    interp_add_kernel<<<(BB * N2) / 4, 256>>>(feats1_ptr, idx_ptr, w_ptr, out);
}

// round 2
// speedup vs baseline: 1.3470x; 1.3470x over previous
#include <cuda_runtime.h>
#include <cuda_bf16.h>
#include <math.h>
#include <stdint.h>

// Problem constants (fixed by the dataset)
#define BB   4
#define N1   4096
#define N2   16384
#define DIM1 512
#define DIM2 256
#define DOUT 256

// Scratch (no allocation allowed -> __device__ globals)
__device__ float g_feats1[BB * N1 * DOUT];          // 16.8 MB
__device__ int   g_idx[BB * N2 * 3];
__device__ float g_w[BB * N2 * 3];

// ---------------------------------------------------------------------------
// Tensor-core GEMM helpers (mma.sync m16n8k16 bf16, fp32 accumulate)
// ---------------------------------------------------------------------------
__device__ __forceinline__ uint32_t smem_u32(const void* p) {
    return (uint32_t)__cvta_generic_to_shared(p);
}

__device__ __forceinline__ void ldsm4(uint32_t* r, uint32_t a) {
    asm volatile("ldmatrix.sync.aligned.m8n8.x4.shared.b16 {%0,%1,%2,%3}, [%4];\n"
        : "=r"(r[0]), "=r"(r[1]), "=r"(r[2]), "=r"(r[3]) : "r"(a));
}

__device__ __forceinline__ void mma16816(float* d, const uint32_t* a, const uint32_t* b) {
    asm volatile(
        "mma.sync.aligned.m16n8k16.row.col.f32.bf16.bf16.f32 "
        "{%0,%1,%2,%3},{%4,%5,%6,%7},{%8,%9},{%0,%1,%2,%3};\n"
        : "+f"(d[0]), "+f"(d[1]), "+f"(d[2]), "+f"(d[3])
        : "r"(a[0]), "r"(a[1]), "r"(a[2]), "r"(a[3]), "r"(b[0]), "r"(b[1]));
}

__device__ __forceinline__ uint32_t pack_bf2(__nv_bfloat16 a, __nv_bfloat16 b) {
    __nv_bfloat162 t; t.x = a; t.y = b;
    return *reinterpret_cast<uint32_t*>(&t);
}

// Swizzled element offset of 8-element (16B) chunk c within row r (32 elems/row).
// chunk' = c ^ ((r>>1)&3) makes 8 consecutive rows of one logical chunk span all
// 32 banks (rows alternate bank halves via r&1; r>>1 permutes the 4 chunk slots).
__device__ __forceinline__ int swz(int r, int c) {
    return r * 32 + ((c ^ ((r >> 1) & 3)) << 3);
}

// Load 16 consecutive fp32 from global, split into bf16 hi/lo, store as two
// swizzled 16B chunks into each of the hi/lo smem tiles.
__device__ __forceinline__ void cvt16(const float* __restrict__ g,
                                      __nv_bfloat16* sh, __nv_bfloat16* sl,
                                      int r, int c0) {
#pragma unroll
    for (int c = 0; c < 2; c++) {
        float4 u = *reinterpret_cast<const float4*>(g + c * 8);
        float4 v = *reinterpret_cast<const float4*>(g + c * 8 + 4);
        float x[8] = {u.x, u.y, u.z, u.w, v.x, v.y, v.z, v.w};
        uint32_t ph[4], pl[4];
#pragma unroll
        for (int i = 0; i < 4; i++) {
            __nv_bfloat16 h0 = __float2bfloat16_rn(x[2 * i]);
            __nv_bfloat16 h1 = __float2bfloat16_rn(x[2 * i + 1]);
            __nv_bfloat16 l0 = __float2bfloat16_rn(x[2 * i]     - __bfloat162float(h0));
            __nv_bfloat16 l1 = __float2bfloat16_rn(x[2 * i + 1] - __bfloat162float(h1));
            ph[i] = pack_bf2(h0, h1);
            pl[i] = pack_bf2(l0, l1);
        }
        int off = swz(r, c0 + c);
        *reinterpret_cast<uint4*>(sh + off) = make_uint4(ph[0], ph[1], ph[2], ph[3]);
        *reinterpret_cast<uint4*>(sl + off) = make_uint4(pl[0], pl[1], pl[2], pl[3]);
    }
}

// ldmatrix x4 address for an A-style 16x16 tile at (row0, chunk c0):
// reg order: (rows, k), (rows+8, k), (rows, k+8), (rows+8, k+8)
__device__ __forceinline__ uint32_t addrA(uint32_t base, int row0, int c0, int lane) {
    int g = lane >> 3;
    int r = row0 + (lane & 7) + ((g & 1) << 3);
    int c = c0 + (g >> 1);
    return base + (uint32_t)(swz(r, c) * 2);
}
// B-style 16(n)x16(k) tile covering two n8 frags:
// reg order: (n, k), (n, k+8), (n+8, k), (n+8, k+8)
__device__ __forceinline__ uint32_t addrB(uint32_t base, int row0, int c0, int lane) {
    int g = lane >> 3;
    int r = row0 + (lane & 7) + ((g >> 1) << 3);
    int c = c0 + (g & 1);
    return base + (uint32_t)(swz(r, c) * 2);
}

// ---------------------------------------------------------------------------
// Fused GEMM (bf16-split tensor core) + BN(eval) + ReLU
//   C[m,n] = relu( (sum_k A[m,k]*W[n,k]) * sc[n] + sh[n] )
// Block tile 64(M) x 256(N=full) x 32(K). 8 warps = 2(m) x 4(n), warp 32x64.
// 3 MMAs per frag pair: Ahi*Bhi + Alo*Bhi + Ahi*Blo (fp32 accumulate).
// M % 64 == 0, K % 32 == 0 (holds: M in {16384,65536}, K in {512,256}).
// ---------------------------------------------------------------------------
__global__ __launch_bounds__(256)
void gemm_mma_bn_relu(const float* __restrict__ A,   // [M,K]
                      const float* __restrict__ W,   // [256,K]
                      const float* __restrict__ bias,
                      const float* __restrict__ gamma,
                      const float* __restrict__ beta,
                      const float* __restrict__ mean,
                      const float* __restrict__ var,
                      float* __restrict__ C,         // [M,256]
                      int M, int K)
{
    __shared__ __align__(16) __nv_bfloat16 Ah[64 * 32],  Al[64 * 32];
    __shared__ __align__(16) __nv_bfloat16 Bh[256 * 32], Bl[256 * 32];
    __shared__ float s_sc[256], s_sh[256];

    const int tid  = threadIdx.x;
    const int lane = tid & 31;
    const int wid  = tid >> 5;
    const int wm   = wid & 1;       // 0..1
    const int wn   = wid >> 1;      // 0..3
    const int m0   = blockIdx.x * 64;

    // BN fold: sc = gamma/sqrt(var+eps); sh = (bias-mean)*sc + beta
    {
        float s = gamma[tid] * rsqrtf(var[tid] + 1e-5f);
        s_sc[tid] = s;
        s_sh[tid] = fmaf(bias[tid] - mean[tid], s, beta[tid]);
    }

    float acc[2][8][4];
#pragma unroll
    for (int i = 0; i < 2; i++)
#pragma unroll
        for (int j = 0; j < 8; j++)
#pragma unroll
            for (int q = 0; q < 4; q++) acc[i][j][q] = 0.f;

    const uint32_t bAh = smem_u32(Ah), bAl = smem_u32(Al);
    const uint32_t bBh = smem_u32(Bh), bBl = smem_u32(Bl);

    for (int k0 = 0; k0 < K; k0 += 32) {
        // A tile: 64 rows x 32 k (128 tasks of 16 floats)
        if (tid < 128) {
            int r = tid >> 1, h = tid & 1;
            cvt16(A + (size_t)(m0 + r) * K + k0 + h * 16, Ah, Al, r, h * 2);
        }
        // B tile: 256 rows x 32 k (512 tasks)
#pragma unroll
        for (int it = 0; it < 2; it++) {
            int t = tid + it * 256;
            int r = t >> 1, h = t & 1;
            cvt16(W + (size_t)r * K + k0 + h * 16, Bh, Bl, r, h * 2);
        }
        __syncthreads();

#pragma unroll
        for (int kk = 0; kk < 2; kk++) {        // two k16 steps
            const int c0 = kk * 2;              // 8-elem chunk index
            uint32_t ah[2][4], al[2][4], bh[4][4], bl[4][4];
#pragma unroll
            for (int mi = 0; mi < 2; mi++) {
                ldsm4(ah[mi], addrA(bAh, wm * 32 + mi * 16, c0, lane));
                ldsm4(al[mi], addrA(bAl, wm * 32 + mi * 16, c0, lane));
            }
#pragma unroll
            for (int j = 0; j < 4; j++) {
                ldsm4(bh[j], addrB(bBh, wn * 64 + j * 16, c0, lane));
                ldsm4(bl[j], addrB(bBl, wn * 64 + j * 16, c0, lane));
            }
#pragma unroll
            for (int mi = 0; mi < 2; mi++)
#pragma unroll
                for (int j = 0; j < 4; j++)
#pragma unroll
                    for (int s = 0; s < 2; s++) {
                        float* d = acc[mi][j * 2 + s];
                        mma16816(d, ah[mi], &bh[j][s * 2]);   // hi*hi
                        mma16816(d, al[mi], &bh[j][s * 2]);   // lo*hi
                        mma16816(d, ah[mi], &bl[j][s * 2]);   // hi*lo
                    }
        }
        __syncthreads();
    }

    // Epilogue: BN + ReLU, write float2 pairs
#pragma unroll
    for (int mi = 0; mi < 2; mi++) {
        int rbase = m0 + wm * 32 + mi * 16 + (lane >> 2);
#pragma unroll
        for (int nf = 0; nf < 8; nf++) {
            int cc = wn * 64 + nf * 8 + 2 * (lane & 3);
            float sc0 = s_sc[cc], sc1 = s_sc[cc + 1];
            float sh0 = s_sh[cc], sh1 = s_sh[cc + 1];
            float* a = acc[mi][nf];
            float2 o0, o1;
            o0.x = fmaxf(fmaf(a[0], sc0, sh0), 0.f);
            o0.y = fmaxf(fmaf(a[1], sc1, sh1), 0.f);
            o1.x = fmaxf(fmaf(a[2], sc0, sh0), 0.f);
            o1.y = fmaxf(fmaf(a[3], sc1, sh1), 0.f);
            *reinterpret_cast<float2*>(&C[(size_t)rbase * DOUT + cc]) = o0;
            *reinterpret_cast<float2*>(&C[(size_t)(rbase + 8) * DOUT + cc]) = o1;
        }
    }
}

// ---------------------------------------------------------------------------
// 3-NN search using the reference's expanded distance form:
//   d = |s|^2 - 2 t.s  (+ |t|^2 folded in after selection; monotone shift)
// Source cloud packed (x,y,z,|s|^2) in dynamic smem (64KB).
// ---------------------------------------------------------------------------
__global__ __launch_bounds__(256)
void knn3_kernel(const float* __restrict__ xyz_tgt,  // [BB,N2,3]
                 const float* __restrict__ xyz_src,  // [BB,N1,3]
                 int* __restrict__ idx,              // [BB*N2,3]
                 float* __restrict__ w)              // [BB*N2,3]
{
    extern __shared__ float4 sp[];                   // N1 float4 = 64KB

    const int b = blockIdx.y;
    const int t = blockIdx.x * 256 + threadIdx.x;

    const float* src = xyz_src + (size_t)b * N1 * 3;
    for (int i = threadIdx.x; i < N1; i += 256) {
        float x = src[3 * i + 0];
        float y = src[3 * i + 1];
        float z = src[3 * i + 2];
        sp[i] = make_float4(x, y, z, x * x + y * y + z * z);
    }
    __syncthreads();

    const float* tp = xyz_tgt + ((size_t)b * N2 + t) * 3;
    const float tx = tp[0], ty = tp[1], tz = tp[2];
    const float mx = -2.f * tx, my = -2.f * ty, mz = -2.f * tz;
    const float t2 = tx * tx + ty * ty + tz * tz;

    float d0 = 3.4e38f, d1 = 3.4e38f, d2 = 3.4e38f;
    int   i0 = 0,       i1 = 0,       i2 = 0;

#pragma unroll 4
    for (int s = 0; s < N1; s++) {
        float4 p = sp[s];
        float d = fmaf(p.x, mx, fmaf(p.y, my, fmaf(p.z, mz, p.w)));
        if (d < d2) {
            if (d < d1) {
                d2 = d1; i2 = i1;
                if (d < d0) { d1 = d0; i1 = i0; d0 = d; i0 = s; }
                else        { d1 = d;  i1 = s; }
            } else {
                d2 = d; i2 = s;
            }
        }
    }

    d0 += t2; d1 += t2; d2 += t2;    // recover true squared distances

    float w0 = 1.f / (d0 + 1e-8f);
    float w1 = 1.f / (d1 + 1e-8f);
    float w2 = 1.f / (d2 + 1e-8f);
    float inv = 1.f / (w0 + w1 + w2);

    size_t o = ((size_t)b * N2 + t) * 3;
    idx[o + 0] = b * N1 + i0;
    idx[o + 1] = b * N1 + i1;
    idx[o + 2] = b * N1 + i2;
    w[o + 0] = w0 * inv;
    w[o + 1] = w1 * inv;
    w[o + 2] = w2 * inv;
}

// ---------------------------------------------------------------------------
// out[r,:] += sum_k w[r,k] * feats1[idx[r,k], :]   (out already holds feats2)
// ---------------------------------------------------------------------------
__global__ __launch_bounds__(256)
void interp_add_kernel(const float* __restrict__ feats1,
                       const int* __restrict__ idx,
                       const float* __restrict__ w,
                       float* __restrict__ out)
{
    const int r  = blockIdx.x * 4 + (threadIdx.x >> 6);
    const int c4 = (threadIdx.x & 63) * 4;

    const int   j0 = idx[r * 3 + 0];
    const int   j1 = idx[r * 3 + 1];
    const int   j2 = idx[r * 3 + 2];
    const float w0 = w[r * 3 + 0];
    const float w1 = w[r * 3 + 1];
    const float w2 = w[r * 3 + 2];

    const float4 f0 = *reinterpret_cast<const float4*>(&feats1[(size_t)j0 * DOUT + c4]);
    const float4 f1 = *reinterpret_cast<const float4*>(&feats1[(size_t)j1 * DOUT + c4]);
    const float4 f2 = *reinterpret_cast<const float4*>(&feats1[(size_t)j2 * DOUT + c4]);

    float4 o = *reinterpret_cast<float4*>(&out[(size_t)r * DOUT + c4]);
    o.x += w0 * f0.x + w1 * f1.x + w2 * f2.x;
    o.y += w0 * f0.y + w1 * f1.y + w2 * f2.y;
    o.z += w0 * f0.z + w1 * f1.z + w2 * f2.z;
    o.w += w0 * f0.w + w1 * f1.w + w2 * f2.w;
    *reinterpret_cast<float4*>(&out[(size_t)r * DOUT + c4]) = o;
}

// ---------------------------------------------------------------------------
extern "C" void kernel_launch(void* const* d_in, const int* in_sizes, int n_in,
                              void* d_out, int out_size)
{
    const float* xyz1    = (const float*)d_in[0];
    const float* points1 = (const float*)d_in[1];
    const float* xyz2    = (const float*)d_in[2];
    const float* points2 = (const float*)d_in[3];
    const float* W1 = (const float*)d_in[4];
    const float* b1 = (const float*)d_in[5];
    const float* g1 = (const float*)d_in[6];
    const float* be1= (const float*)d_in[7];
    const float* m1 = (const float*)d_in[8];
    const float* v1 = (const float*)d_in[9];
    const float* W2 = (const float*)d_in[10];
    const float* b2 = (const float*)d_in[11];
    const float* g2 = (const float*)d_in[12];
    const float* be2= (const float*)d_in[13];
    const float* m2 = (const float*)d_in[14];
    const float* v2 = (const float*)d_in[15];
    float* out = (float*)d_out;

    float* feats1_ptr = nullptr;
    int*   idx_ptr    = nullptr;
    float* w_ptr      = nullptr;
    cudaGetSymbolAddress((void**)&feats1_ptr, g_feats1);
    cudaGetSymbolAddress((void**)&idx_ptr,    g_idx);
    cudaGetSymbolAddress((void**)&w_ptr,      g_w);

    // 64KB dynamic smem for KNN source cache
    static int knn_attr_set = 0;
    if (!knn_attr_set) {
        cudaFuncSetAttribute(knn3_kernel,
                             cudaFuncAttributeMaxDynamicSharedMemorySize,
                             N1 * (int)sizeof(float4));
        knn_attr_set = 1;
    }

    // KNN (independent of GEMMs)
    knn3_kernel<<<dim3(N2 / 256, BB), 256, N1 * sizeof(float4)>>>(
        xyz2, xyz1, idx_ptr, w_ptr);

    // feats1 = relu(BN(points1 @ W1^T + b1))  -> scratch
    gemm_mma_bn_relu<<<(BB * N1) / 64, 256>>>(
        points1, W1, b1, g1, be1, m1, v1, feats1_ptr, BB * N1, DIM1);

    // feats2 = relu(BN(points2 @ W2^T + b2))  -> d_out
    gemm_mma_bn_relu<<<(BB * N2) / 64, 256>>>(
        points2, W2, b2, g2, be2, m2, v2, out, BB * N2, DIM2);

    // out += 3-NN weighted interpolation of feats1
    interp_add_kernel<<<(BB * N2) / 4, 256>>>(feats1_ptr, idx_ptr, w_ptr, out);
}

// round 3
// speedup vs baseline: 1.5690x; 1.1648x over previous
#include <cuda_runtime.h>
#include <cuda_bf16.h>
#include <math.h>
#include <stdint.h>

// Problem constants (fixed by the dataset)
#define BB   4
#define N1   4096
#define N2   16384
#define DIM1 512
#define DIM2 256
#define DOUT 256

// Scratch (no allocation allowed -> __device__ globals)
__device__ float g_feats1[BB * N1 * DOUT];          // 16.8 MB
__device__ int   g_idx[BB * N2 * 3];
__device__ float g_w[BB * N2 * 3];
// Pre-split bf16 operands (hi/lo 2-term decomposition of fp32)
__device__ __nv_bfloat16 g_p1h[BB * N1 * DIM1], g_p1l[BB * N1 * DIM1];   // 16.8MB x2
__device__ __nv_bfloat16 g_p2h[BB * N2 * DIM2], g_p2l[BB * N2 * DIM2];   // 33.5MB x2
__device__ __nv_bfloat16 g_w1h[DOUT * DIM1], g_w1l[DOUT * DIM1];
__device__ __nv_bfloat16 g_w2h[DOUT * DIM2], g_w2l[DOUT * DIM2];

// ---------------------------------------------------------------------------
// Helpers
// ---------------------------------------------------------------------------
__device__ __forceinline__ uint32_t smem_u32(const void* p) {
    return (uint32_t)__cvta_generic_to_shared(p);
}
__device__ __forceinline__ void ldsm4(uint32_t* r, uint32_t a) {
    asm volatile("ldmatrix.sync.aligned.m8n8.x4.shared.b16 {%0,%1,%2,%3}, [%4];\n"
        : "=r"(r[0]), "=r"(r[1]), "=r"(r[2]), "=r"(r[3]) : "r"(a));
}
__device__ __forceinline__ void mma16816(float* d, const uint32_t* a, const uint32_t* b) {
    asm volatile(
        "mma.sync.aligned.m16n8k16.row.col.f32.bf16.bf16.f32 "
        "{%0,%1,%2,%3},{%4,%5,%6,%7},{%8,%9},{%0,%1,%2,%3};\n"
        : "+f"(d[0]), "+f"(d[1]), "+f"(d[2]), "+f"(d[3])
        : "r"(a[0]), "r"(a[1]), "r"(a[2]), "r"(a[3]), "r"(b[0]), "r"(b[1]));
}
__device__ __forceinline__ uint32_t pack_bf2(__nv_bfloat16 a, __nv_bfloat16 b) {
    __nv_bfloat162 t; t.x = a; t.y = b;
    return *reinterpret_cast<uint32_t*>(&t);
}
__device__ __forceinline__ void cpasync16(uint32_t dst, const void* src) {
    asm volatile("cp.async.cg.shared.global [%0], [%1], 16;\n"
        :: "r"(dst), "l"(src) : "memory");
}
__device__ __forceinline__ void cp_commit() {
    asm volatile("cp.async.commit_group;\n" ::: "memory");
}
template <int N> __device__ __forceinline__ void cp_wait() {
    asm volatile("cp.async.wait_group %0;\n" :: "n"(N) : "memory");
}

// Swizzled element offset of 8-element (16B) chunk c within row r (32 elems/row)
__device__ __forceinline__ int swz(int r, int c) {
    return r * 32 + ((c ^ ((r >> 1) & 3)) << 3);
}
// ldmatrix x4 address, A-style 16x16 tile at (row0, chunk c0) (byte base)
__device__ __forceinline__ uint32_t addrA(uint32_t base, int row0, int c0, int lane) {
    int g = lane >> 3;
    int r = row0 + (lane & 7) + ((g & 1) << 3);
    int c = c0 + (g >> 1);
    return base + (uint32_t)(swz(r, c) * 2);
}
// B-style 16(n)x16(k) tile covering two n8 frags
__device__ __forceinline__ uint32_t addrB(uint32_t base, int row0, int c0, int lane) {
    int g = lane >> 3;
    int r = row0 + (lane & 7) + ((g >> 1) << 3);
    int c = c0 + (g & 1);
    return base + (uint32_t)(swz(r, c) * 2);
}

// ---------------------------------------------------------------------------
// fp32 -> (hi, lo) bf16 split, elementwise. n4 = count/4.
// ---------------------------------------------------------------------------
__global__ __launch_bounds__(256)
void split_bf16_kernel(const float* __restrict__ x,
                       __nv_bfloat16* __restrict__ hi,
                       __nv_bfloat16* __restrict__ lo, int n4)
{
    int i = blockIdx.x * 256 + threadIdx.x;
    if (i >= n4) return;
    float4 v = reinterpret_cast<const float4*>(x)[i];
    float xs[4] = {v.x, v.y, v.z, v.w};
    uint32_t hp[2], lp[2];
#pragma unroll
    for (int k = 0; k < 2; k++) {
        __nv_bfloat16 h0 = __float2bfloat16_rn(xs[2 * k]);
        __nv_bfloat16 h1 = __float2bfloat16_rn(xs[2 * k + 1]);
        __nv_bfloat16 l0 = __float2bfloat16_rn(xs[2 * k]     - __bfloat162float(h0));
        __nv_bfloat16 l1 = __float2bfloat16_rn(xs[2 * k + 1] - __bfloat162float(h1));
        hp[k] = pack_bf2(h0, h1);
        lp[k] = pack_bf2(l0, l1);
    }
    reinterpret_cast<uint2*>(hi)[i] = make_uint2(hp[0], hp[1]);
    reinterpret_cast<uint2*>(lo)[i] = make_uint2(lp[0], lp[1]);
}

// ---------------------------------------------------------------------------
// GEMM (pre-split bf16 operands, 3-term MMA) + BN(eval) + ReLU
// + optional fused 3-NN interpolation add (for the second GEMM).
// Block tile 64(M) x 256(N) x 32(K); 8 warps = 2(m) x 4(n); warp 32x64.
// Double-buffered cp.async. Dynamic smem: 2 stages x 40KB + 2KB BN.
// ---------------------------------------------------------------------------
#define STG_BYTES 40960
__global__ __launch_bounds__(256)
void gemm_mma_bn_relu(const __nv_bfloat16* __restrict__ Ah_g,
                      const __nv_bfloat16* __restrict__ Al_g,
                      const __nv_bfloat16* __restrict__ Wh_g,
                      const __nv_bfloat16* __restrict__ Wl_g,
                      const float* __restrict__ bias,
                      const float* __restrict__ gamma,
                      const float* __restrict__ beta,
                      const float* __restrict__ mean,
                      const float* __restrict__ var,
                      float* __restrict__ C,         // [M,256]
                      int M, int K,
                      const float* __restrict__ itpF,   // feats1 or null
                      const int*   __restrict__ itpI,
                      const float* __restrict__ itpW)
{
    extern __shared__ __align__(16) char smem[];
    float* s_sc = reinterpret_cast<float*>(smem + 2 * STG_BYTES);
    float* s_sh = s_sc + 256;

    const int tid  = threadIdx.x;
    const int lane = tid & 31;
    const int wid  = tid >> 5;
    const int wm   = wid & 1;
    const int wn   = wid >> 1;
    const int m0   = blockIdx.x * 64;

    {   // BN fold
        float s = gamma[tid] * rsqrtf(var[tid] + 1e-5f);
        s_sc[tid] = s;
        s_sh[tid] = fmaf(bias[tid] - mean[tid], s, beta[tid]);
    }

    float acc[2][8][4];
#pragma unroll
    for (int i = 0; i < 2; i++)
#pragma unroll
        for (int j = 0; j < 8; j++)
#pragma unroll
            for (int q = 0; q < 4; q++) acc[i][j][q] = 0.f;

    const int arow = tid >> 2, akc = tid & 3;          // A chunk assignment
    const int aswz = swz(arow, akc) * 2;
    const size_t asrc = (size_t)(m0 + arow) * K + akc * 8;

    auto issue = [&](int it) {
        const int k0 = it * 32;
        const uint32_t base = smem_u32(smem) + (it & 1) * STG_BYTES;
        cpasync16(base + aswz,        Ah_g + asrc + k0);
        cpasync16(base + 4096 + aswz, Al_g + asrc + k0);
#pragma unroll
        for (int j = 0; j < 4; j++) {
            int cb  = tid + j * 256;
            int row = cb >> 2, kc = cb & 3;
            int d   = swz(row, kc) * 2;
            size_t s = (size_t)row * K + k0 + kc * 8;
            cpasync16(base + 8192  + d, Wh_g + s);
            cpasync16(base + 24576 + d, Wl_g + s);
        }
        cp_commit();
    };

    const int T = K / 32;
    issue(0);

    for (int it = 0; it < T; it++) {
        if (it + 1 < T) { issue(it + 1); cp_wait<1>(); }
        else            { cp_wait<0>(); }
        __syncthreads();

        const uint32_t bA = smem_u32(smem) + (it & 1) * STG_BYTES;
        const uint32_t bAh = bA, bAl = bA + 4096;
        const uint32_t bBh = bA + 8192, bBl = bA + 24576;

#pragma unroll
        for (int kk = 0; kk < 2; kk++) {
            const int c0 = kk * 2;
            uint32_t ah[2][4], al[2][4], bh[4][4], bl[4][4];
#pragma unroll
            for (int mi = 0; mi < 2; mi++) {
                ldsm4(ah[mi], addrA(bAh, wm * 32 + mi * 16, c0, lane));
                ldsm4(al[mi], addrA(bAl, wm * 32 + mi * 16, c0, lane));
            }
#pragma unroll
            for (int j = 0; j < 4; j++) {
                ldsm4(bh[j], addrB(bBh, wn * 64 + j * 16, c0, lane));
                ldsm4(bl[j], addrB(bBl, wn * 64 + j * 16, c0, lane));
            }
#pragma unroll
            for (int mi = 0; mi < 2; mi++)
#pragma unroll
                for (int j = 0; j < 4; j++)
#pragma unroll
                    for (int s = 0; s < 2; s++) {
                        float* d = acc[mi][j * 2 + s];
                        mma16816(d, ah[mi], &bh[j][s * 2]);   // hi*hi
                        mma16816(d, al[mi], &bh[j][s * 2]);   // lo*hi
                        mma16816(d, ah[mi], &bl[j][s * 2]);   // hi*lo
                    }
        }
        __syncthreads();
    }

    // Epilogue: BN + ReLU (+ fused interp add)
    const bool fuse = (itpF != nullptr);
#pragma unroll
    for (int mi = 0; mi < 2; mi++) {
        const int r0 = m0 + wm * 32 + mi * 16 + (lane >> 2);
        const int r1 = r0 + 8;
        int ja[3], jb[3];
        float wa[3], wb[3];
        if (fuse) {
#pragma unroll
            for (int k = 0; k < 3; k++) {
                ja[k] = itpI[r0 * 3 + k];  wa[k] = itpW[r0 * 3 + k];
                jb[k] = itpI[r1 * 3 + k];  wb[k] = itpW[r1 * 3 + k];
            }
        }
#pragma unroll
        for (int nf = 0; nf < 8; nf++) {
            const int cc = wn * 64 + nf * 8 + 2 * (lane & 3);
            const float sc0 = s_sc[cc], sc1 = s_sc[cc + 1];
            const float sh0 = s_sh[cc], sh1 = s_sh[cc + 1];
            float* a = acc[mi][nf];
            float2 o0, o1;
            o0.x = fmaxf(fmaf(a[0], sc0, sh0), 0.f);
            o0.y = fmaxf(fmaf(a[1], sc1, sh1), 0.f);
            o1.x = fmaxf(fmaf(a[2], sc0, sh0), 0.f);
            o1.y = fmaxf(fmaf(a[3], sc1, sh1), 0.f);
            if (fuse) {
#pragma unroll
                for (int k = 0; k < 3; k++) {
                    float2 f = *reinterpret_cast<const float2*>(
                        &itpF[(size_t)ja[k] * DOUT + cc]);
                    o0.x = fmaf(wa[k], f.x, o0.x);
                    o0.y = fmaf(wa[k], f.y, o0.y);
                    float2 g = *reinterpret_cast<const float2*>(
                        &itpF[(size_t)jb[k] * DOUT + cc]);
                    o1.x = fmaf(wb[k], g.x, o1.x);
                    o1.y = fmaf(wb[k], g.y, o1.y);
                }
            }
            *reinterpret_cast<float2*>(&C[(size_t)r0 * DOUT + cc]) = o0;
            *reinterpret_cast<float2*>(&C[(size_t)r1 * DOUT + cc]) = o1;
        }
    }
}

// ---------------------------------------------------------------------------
// 3-NN search (reference's expanded distance form)
// ---------------------------------------------------------------------------
__global__ __launch_bounds__(256)
void knn3_kernel(const float* __restrict__ xyz_tgt,
                 const float* __restrict__ xyz_src,
                 int* __restrict__ idx,
                 float* __restrict__ w)
{
    extern __shared__ float4 sp[];                   // N1 float4 = 64KB

    const int b = blockIdx.y;
    const int t = blockIdx.x * 256 + threadIdx.x;

    const float* src = xyz_src + (size_t)b * N1 * 3;
    for (int i = threadIdx.x; i < N1; i += 256) {
        float x = src[3 * i + 0];
        float y = src[3 * i + 1];
        float z = src[3 * i + 2];
        sp[i] = make_float4(x, y, z, x * x + y * y + z * z);
    }
    __syncthreads();

    const float* tp = xyz_tgt + ((size_t)b * N2 + t) * 3;
    const float tx = tp[0], ty = tp[1], tz = tp[2];
    const float mx = -2.f * tx, my = -2.f * ty, mz = -2.f * tz;
    const float t2 = tx * tx + ty * ty + tz * tz;

    float d0 = 3.4e38f, d1 = 3.4e38f, d2 = 3.4e38f;
    int   i0 = 0,       i1 = 0,       i2 = 0;

#pragma unroll 4
    for (int s = 0; s < N1; s++) {
        float4 p = sp[s];
        float d = fmaf(p.x, mx, fmaf(p.y, my, fmaf(p.z, mz, p.w)));
        if (d < d2) {
            if (d < d1) {
                d2 = d1; i2 = i1;
                if (d < d0) { d1 = d0; i1 = i0; d0 = d; i0 = s; }
                else        { d1 = d;  i1 = s; }
            } else {
                d2 = d; i2 = s;
            }
        }
    }

    d0 += t2; d1 += t2; d2 += t2;

    float w0 = 1.f / (d0 + 1e-8f);
    float w1 = 1.f / (d1 + 1e-8f);
    float w2 = 1.f / (d2 + 1e-8f);
    float inv = 1.f / (w0 + w1 + w2);

    size_t o = ((size_t)b * N2 + t) * 3;
    idx[o + 0] = b * N1 + i0;
    idx[o + 1] = b * N1 + i1;
    idx[o + 2] = b * N1 + i2;
    w[o + 0] = w0 * inv;
    w[o + 1] = w1 * inv;
    w[o + 2] = w2 * inv;
}

// ---------------------------------------------------------------------------
extern "C" void kernel_launch(void* const* d_in, const int* in_sizes, int n_in,
                              void* d_out, int out_size)
{
    const float* xyz1    = (const float*)d_in[0];
    const float* points1 = (const float*)d_in[1];
    const float* xyz2    = (const float*)d_in[2];
    const float* points2 = (const float*)d_in[3];
    const float* W1 = (const float*)d_in[4];
    const float* b1 = (const float*)d_in[5];
    const float* g1 = (const float*)d_in[6];
    const float* be1= (const float*)d_in[7];
    const float* m1 = (const float*)d_in[8];
    const float* v1 = (const float*)d_in[9];
    const float* W2 = (const float*)d_in[10];
    const float* b2 = (const float*)d_in[11];
    const float* g2 = (const float*)d_in[12];
    const float* be2= (const float*)d_in[13];
    const float* m2 = (const float*)d_in[14];
    const float* v2 = (const float*)d_in[15];
    float* out = (float*)d_out;

    float* feats1_ptr = nullptr;
    int*   idx_ptr    = nullptr;
    float* w_ptr      = nullptr;
    __nv_bfloat16 *p1h, *p1l, *p2h, *p2l, *w1h, *w1l, *w2h, *w2l;
    cudaGetSymbolAddress((void**)&feats1_ptr, g_feats1);
    cudaGetSymbolAddress((void**)&idx_ptr,    g_idx);
    cudaGetSymbolAddress((void**)&w_ptr,      g_w);
    cudaGetSymbolAddress((void**)&p1h, g_p1h);
    cudaGetSymbolAddress((void**)&p1l, g_p1l);
    cudaGetSymbolAddress((void**)&p2h, g_p2h);
    cudaGetSymbolAddress((void**)&p2l, g_p2l);
    cudaGetSymbolAddress((void**)&w1h, g_w1h);
    cudaGetSymbolAddress((void**)&w1l, g_w1l);
    cudaGetSymbolAddress((void**)&w2h, g_w2h);
    cudaGetSymbolAddress((void**)&w2l, g_w2l);

    static int attr_set = 0;
    if (!attr_set) {
        cudaFuncSetAttribute(knn3_kernel,
                             cudaFuncAttributeMaxDynamicSharedMemorySize,
                             N1 * (int)sizeof(float4));
        cudaFuncSetAttribute(gemm_mma_bn_relu,
                             cudaFuncAttributeMaxDynamicSharedMemorySize,
                             2 * STG_BYTES + 2048);
        attr_set = 1;
    }

    // Operand pre-splitting (fp32 -> bf16 hi/lo), memory-bound
    {
        int n4;
        n4 = BB * N1 * DIM1 / 4;
        split_bf16_kernel<<<(n4 + 255) / 256, 256>>>(points1, p1h, p1l, n4);
        n4 = BB * N2 * DIM2 / 4;
        split_bf16_kernel<<<(n4 + 255) / 256, 256>>>(points2, p2h, p2l, n4);
        n4 = DOUT * DIM1 / 4;
        split_bf16_kernel<<<(n4 + 255) / 256, 256>>>(W1, w1h, w1l, n4);
        n4 = DOUT * DIM2 / 4;
        split_bf16_kernel<<<(n4 + 255) / 256, 256>>>(W2, w2h, w2l, n4);
    }

    // KNN
    knn3_kernel<<<dim3(N2 / 256, BB), 256, N1 * sizeof(float4)>>>(
        xyz2, xyz1, idx_ptr, w_ptr);

    // feats1 = relu(BN(points1 @ W1^T + b1)) -> scratch
    gemm_mma_bn_relu<<<(BB * N1) / 64, 256, 2 * STG_BYTES + 2048>>>(
        p1h, p1l, w1h, w1l, b1, g1, be1, m1, v1,
        feats1_ptr, BB * N1, DIM1, nullptr, nullptr, nullptr);

    // out = relu(BN(points2 @ W2^T + b2)) + interp(feats1)   [fused]
    gemm_mma_bn_relu<<<(BB * N2) / 64, 256, 2 * STG_BYTES + 2048>>>(
        p2h, p2l, w2h, w2l, b2, g2, be2, m2, v2,
        out, BB * N2, DIM2, feats1_ptr, idx_ptr, w_ptr);
}

// round 5
// speedup vs baseline: 1.6474x; 1.0500x over previous
#include <cuda_runtime.h>
#include <cuda_bf16.h>
#include <math.h>
#include <stdint.h>

// Problem constants (fixed by the dataset)
#define BB   4
#define N1   4096
#define N2   16384
#define DIM1 512
#define DIM2 256
#define DOUT 256

// Scratch (no allocation allowed -> __device__ globals)
__device__ float g_feats1[BB * N1 * DOUT];
__device__ int   g_idx[BB * N2 * 3];
__device__ float g_w[BB * N2 * 3];
__device__ __nv_bfloat16 g_p1h[BB * N1 * DIM1], g_p1l[BB * N1 * DIM1];
__device__ __nv_bfloat16 g_p2h[BB * N2 * DIM2], g_p2l[BB * N2 * DIM2];
__device__ __nv_bfloat16 g_w1h[DOUT * DIM1], g_w1l[DOUT * DIM1];
__device__ __nv_bfloat16 g_w2h[DOUT * DIM2], g_w2l[DOUT * DIM2];

// ---------------------------------------------------------------------------
// Helpers
// ---------------------------------------------------------------------------
__device__ __forceinline__ uint32_t smem_u32(const void* p) {
    return (uint32_t)__cvta_generic_to_shared(p);
}
__device__ __forceinline__ void ldsm4(uint32_t* r, uint32_t a) {
    asm volatile("ldmatrix.sync.aligned.m8n8.x4.shared.b16 {%0,%1,%2,%3}, [%4];\n"
        : "=r"(r[0]), "=r"(r[1]), "=r"(r[2]), "=r"(r[3]) : "r"(a));
}
__device__ __forceinline__ void mma16816(float* d, const uint32_t* a, const uint32_t* b) {
    asm volatile(
        "mma.sync.aligned.m16n8k16.row.col.f32.bf16.bf16.f32 "
        "{%0,%1,%2,%3},{%4,%5,%6,%7},{%8,%9},{%0,%1,%2,%3};\n"
        : "+f"(d[0]), "+f"(d[1]), "+f"(d[2]), "+f"(d[3])
        : "r"(a[0]), "r"(a[1]), "r"(a[2]), "r"(a[3]), "r"(b[0]), "r"(b[1]));
}
__device__ __forceinline__ uint32_t pack_bf2(__nv_bfloat16 a, __nv_bfloat16 b) {
    __nv_bfloat162 t; t.x = a; t.y = b;
    return *reinterpret_cast<uint32_t*>(&t);
}
__device__ __forceinline__ void cpasync16(uint32_t dst, const void* src) {
    asm volatile("cp.async.cg.shared.global [%0], [%1], 16;\n"
        :: "r"(dst), "l"(src) : "memory");
}
__device__ __forceinline__ void cp_commit() {
    asm volatile("cp.async.commit_group;\n" ::: "memory");
}
template <int N> __device__ __forceinline__ void cp_wait() {
    asm volatile("cp.async.wait_group %0;\n" :: "n"(N) : "memory");
}

// Swizzled element offset of 8-element (16B) chunk c within row r (32 elems/row)
__device__ __forceinline__ int swz(int r, int c) {
    return r * 32 + ((c ^ ((r >> 1) & 3)) << 3);
}
// ldmatrix x4 address, A-style 16x16 tile at (row0, chunk c0) (byte base)
__device__ __forceinline__ uint32_t addrA(uint32_t base, int row0, int c0, int lane) {
    int g = lane >> 3;
    int r = row0 + (lane & 7) + ((g & 1) << 3);
    int c = c0 + (g >> 1);
    return base + (uint32_t)(swz(r, c) * 2);
}
// B-style 16(n)x16(k) tile covering two n8 frags
__device__ __forceinline__ uint32_t addrB(uint32_t base, int row0, int c0, int lane) {
    int g = lane >> 3;
    int r = row0 + (lane & 7) + ((g >> 1) << 3);
    int c = c0 + (g & 1);
    return base + (uint32_t)(swz(r, c) * 2);
}

// ---------------------------------------------------------------------------
// fp32 -> (hi, lo) bf16 split, elementwise. n4 = count/4.
// ---------------------------------------------------------------------------
__global__ __launch_bounds__(256)
void split_bf16_kernel(const float* __restrict__ x,
                       __nv_bfloat16* __restrict__ hi,
                       __nv_bfloat16* __restrict__ lo, int n4)
{
    int i = blockIdx.x * 256 + threadIdx.x;
    if (i >= n4) return;
    float4 v = reinterpret_cast<const float4*>(x)[i];
    float xs[4] = {v.x, v.y, v.z, v.w};
    uint32_t hp[2], lp[2];
#pragma unroll
    for (int k = 0; k < 2; k++) {
        __nv_bfloat16 h0 = __float2bfloat16_rn(xs[2 * k]);
        __nv_bfloat16 h1 = __float2bfloat16_rn(xs[2 * k + 1]);
        __nv_bfloat16 l0 = __float2bfloat16_rn(xs[2 * k]     - __bfloat162float(h0));
        __nv_bfloat16 l1 = __float2bfloat16_rn(xs[2 * k + 1] - __bfloat162float(h1));
        hp[k] = pack_bf2(h0, h1);
        lp[k] = pack_bf2(l0, l1);
    }
    reinterpret_cast<uint2*>(hi)[i] = make_uint2(hp[0], hp[1]);
    reinterpret_cast<uint2*>(lo)[i] = make_uint2(lp[0], lp[1]);
}

// ---------------------------------------------------------------------------
// GEMM (pre-split bf16, 3-term mma.sync) + BN(eval) + ReLU (+ fused interp)
// Block 64(M) x 128(N) x 32(K); 128 threads = 4 warps (2m x 2n); warp 32x64.
// 3-stage cp.async pipeline, ONE __syncthreads per K-tile.
// Stage smem 24KB: Ah(4K) Al(4K) Bh(8K) Bl(8K). 3 stages -> 3 CTAs/SM.
// Grid: (M/64, 2) — blockIdx.y picks the 128-wide N half.
// ---------------------------------------------------------------------------
#define STG 24576
#define GSM_SC (3 * STG)
#define GSM_SH (3 * STG + 1024)
#define GSM_TOTAL (3 * STG + 2048)

__global__ __launch_bounds__(128, 3)
void gemm_mma_bn_relu(const __nv_bfloat16* __restrict__ Ah_g,
                      const __nv_bfloat16* __restrict__ Al_g,
                      const __nv_bfloat16* __restrict__ Wh_g,
                      const __nv_bfloat16* __restrict__ Wl_g,
                      const float* __restrict__ bias,
                      const float* __restrict__ gamma,
                      const float* __restrict__ beta,
                      const float* __restrict__ mean,
                      const float* __restrict__ var,
                      float* __restrict__ C,         // [M,256]
                      int K,
                      const float* __restrict__ itpF,   // feats1 or null
                      const int*   __restrict__ itpI,
                      const float* __restrict__ itpW)
{
    extern __shared__ __align__(16) char smem[];
    float* s_sc = reinterpret_cast<float*>(smem + GSM_SC);
    float* s_sh = reinterpret_cast<float*>(smem + GSM_SH);

    const int tid  = threadIdx.x;
    const int lane = tid & 31;
    const int wid  = tid >> 5;
    const int wm   = wid & 1;       // 0..1 (m)
    const int wn   = wid >> 1;      // 0..1 (n)
    const int m0   = blockIdx.x * 64;
    const int n0   = blockIdx.y * 128;

    // BN fold (all 256 channels; only this block's 128 used)
#pragma unroll
    for (int c = tid; c < 256; c += 128) {
        float s = gamma[c] * rsqrtf(var[c] + 1e-5f);
        s_sc[c] = s;
        s_sh[c] = fmaf(bias[c] - mean[c], s, beta[c]);
    }

    float acc[2][8][4];
#pragma unroll
    for (int i = 0; i < 2; i++)
#pragma unroll
        for (int j = 0; j < 8; j++)
#pragma unroll
            for (int q = 0; q < 4; q++) acc[i][j][q] = 0.f;

    const uint32_t sb = smem_u32(smem);

    auto issue = [&](int it) {
        const int k0 = it * 32;
        const uint32_t base = sb + (it % 3) * STG;
        // A: 64 rows x 4 chunks = 256 chunk slots (x2 hi/lo)
#pragma unroll
        for (int c = tid; c < 256; c += 128) {
            int row = c >> 2, kc = c & 3;
            int d = swz(row, kc) * 2;
            size_t s = (size_t)(m0 + row) * K + k0 + kc * 8;
            cpasync16(base + d,        Ah_g + s);
            cpasync16(base + 4096 + d, Al_g + s);
        }
        // B: 128 rows x 4 chunks = 512 chunk slots (x2 hi/lo)
#pragma unroll
        for (int c = tid; c < 512; c += 128) {
            int row = c >> 2, kc = c & 3;
            int d = swz(row, kc) * 2;
            size_t s = (size_t)(n0 + row) * K + k0 + kc * 8;
            cpasync16(base + 8192  + d, Wh_g + s);
            cpasync16(base + 16384 + d, Wl_g + s);
        }
    };

    const int T = K / 32;
    issue(0); cp_commit();
    issue(1); cp_commit();

    for (int it = 0; it < T; it++) {
        cp_wait<1>();          // tile it arrived (this thread's groups)
        __syncthreads();       // visibility + all warps past compute(it-1)
        if (it + 2 < T) issue(it + 2);
        cp_commit();           // empty group keeps the count aligned at tail

        const uint32_t bA  = sb + (it % 3) * STG;
        const uint32_t bAh = bA, bAl = bA + 4096;
        const uint32_t bBh = bA + 8192, bBl = bA + 16384;

#pragma unroll
        for (int kk = 0; kk < 2; kk++) {
            const int c0 = kk * 2;
            uint32_t ah[2][4], al[2][4];
#pragma unroll
            for (int mi = 0; mi < 2; mi++) {
                ldsm4(ah[mi], addrA(bAh, wm * 32 + mi * 16, c0, lane));
                ldsm4(al[mi], addrA(bAl, wm * 32 + mi * 16, c0, lane));
            }
#pragma unroll
            for (int j = 0; j < 4; j++) {
                uint32_t bh[4], bl[4];
                ldsm4(bh, addrB(bBh, wn * 64 + j * 16, c0, lane));
                ldsm4(bl, addrB(bBl, wn * 64 + j * 16, c0, lane));
#pragma unroll
                for (int mi = 0; mi < 2; mi++)
#pragma unroll
                    for (int s = 0; s < 2; s++) {
                        float* d = acc[mi][j * 2 + s];
                        mma16816(d, ah[mi], &bh[s * 2]);   // hi*hi
                        mma16816(d, al[mi], &bh[s * 2]);   // lo*hi
                        mma16816(d, ah[mi], &bl[s * 2]);   // hi*lo
                    }
            }
        }
    }

    // Epilogue: BN + ReLU (+ fused interp add)
    const bool fuse = (itpF != nullptr);
#pragma unroll
    for (int mi = 0; mi < 2; mi++) {
        const int r0 = m0 + wm * 32 + mi * 16 + (lane >> 2);
        const int r1 = r0 + 8;
        int ja[3], jb[3];
        float wa[3], wb[3];
        if (fuse) {
#pragma unroll
            for (int k = 0; k < 3; k++) {
                ja[k] = itpI[r0 * 3 + k];  wa[k] = itpW[r0 * 3 + k];
                jb[k] = itpI[r1 * 3 + k];  wb[k] = itpW[r1 * 3 + k];
            }
        }
#pragma unroll
        for (int nf = 0; nf < 8; nf++) {
            const int cc = n0 + wn * 64 + nf * 8 + 2 * (lane & 3);
            const float sc0 = s_sc[cc], sc1 = s_sc[cc + 1];
            const float sh0 = s_sh[cc], sh1 = s_sh[cc + 1];
            float* a = acc[mi][nf];
            float2 o0, o1;
            o0.x = fmaxf(fmaf(a[0], sc0, sh0), 0.f);
            o0.y = fmaxf(fmaf(a[1], sc1, sh1), 0.f);
            o1.x = fmaxf(fmaf(a[2], sc0, sh0), 0.f);
            o1.y = fmaxf(fmaf(a[3], sc1, sh1), 0.f);
            if (fuse) {
#pragma unroll
                for (int k = 0; k < 3; k++) {
                    float2 f = *reinterpret_cast<const float2*>(
                        &itpF[(size_t)ja[k] * DOUT + cc]);
                    o0.x = fmaf(wa[k], f.x, o0.x);
                    o0.y = fmaf(wa[k], f.y, o0.y);
                    float2 g = *reinterpret_cast<const float2*>(
                        &itpF[(size_t)jb[k] * DOUT + cc]);
                    o1.x = fmaf(wb[k], g.x, o1.x);
                    o1.y = fmaf(wb[k], g.y, o1.y);
                }
            }
            *reinterpret_cast<float2*>(&C[(size_t)r0 * DOUT + cc]) = o0;
            *reinterpret_cast<float2*>(&C[(size_t)r1 * DOUT + cc]) = o1;
        }
    }
}

// ---------------------------------------------------------------------------
// 3-NN search (reference's expanded distance form)
// ---------------------------------------------------------------------------
__global__ __launch_bounds__(256)
void knn3_kernel(const float* __restrict__ xyz_tgt,
                 const float* __restrict__ xyz_src,
                 int* __restrict__ idx,
                 float* __restrict__ w)
{
    extern __shared__ float4 sp[];                   // N1 float4 = 64KB

    const int b = blockIdx.y;
    const int t = blockIdx.x * 256 + threadIdx.x;

    const float* src = xyz_src + (size_t)b * N1 * 3;
    for (int i = threadIdx.x; i < N1; i += 256) {
        float x = src[3 * i + 0];
        float y = src[3 * i + 1];
        float z = src[3 * i + 2];
        sp[i] = make_float4(x, y, z, x * x + y * y + z * z);
    }
    __syncthreads();

    const float* tp = xyz_tgt + ((size_t)b * N2 + t) * 3;
    const float tx = tp[0], ty = tp[1], tz = tp[2];
    const float mx = -2.f * tx, my = -2.f * ty, mz = -2.f * tz;
    const float t2 = tx * tx + ty * ty + tz * tz;

    float d0 = 3.4e38f, d1 = 3.4e38f, d2 = 3.4e38f;
    int   i0 = 0,       i1 = 0,       i2 = 0;

#pragma unroll 4
    for (int s = 0; s < N1; s++) {
        float4 p = sp[s];
        float d = fmaf(p.x, mx, fmaf(p.y, my, fmaf(p.z, mz, p.w)));
        if (d < d2) {
            if (d < d1) {
                d2 = d1; i2 = i1;
                if (d < d0) { d1 = d0; i1 = i0; d0 = d; i0 = s; }
                else        { d1 = d;  i1 = s; }
            } else {
                d2 = d; i2 = s;
            }
        }
    }

    d0 += t2; d1 += t2; d2 += t2;

    float w0 = 1.f / (d0 + 1e-8f);
    float w1 = 1.f / (d1 + 1e-8f);
    float w2 = 1.f / (d2 + 1e-8f);
    float inv = 1.f / (w0 + w1 + w2);

    size_t o = ((size_t)b * N2 + t) * 3;
    idx[o + 0] = b * N1 + i0;
    idx[o + 1] = b * N1 + i1;
    idx[o + 2] = b * N1 + i2;
    w[o + 0] = w0 * inv;
    w[o + 1] = w1 * inv;
    w[o + 2] = w2 * inv;
}

// ---------------------------------------------------------------------------
extern "C" void kernel_launch(void* const* d_in, const int* in_sizes, int n_in,
                              void* d_out, int out_size)
{
    const float* xyz1    = (const float*)d_in[0];
    const float* points1 = (const float*)d_in[1];
    const float* xyz2    = (const float*)d_in[2];
    const float* points2 = (const float*)d_in[3];
    const float* W1 = (const float*)d_in[4];
    const float* b1 = (const float*)d_in[5];
    const float* g1 = (const float*)d_in[6];
    const float* be1= (const float*)d_in[7];
    const float* m1 = (const float*)d_in[8];
    const float* v1 = (const float*)d_in[9];
    const float* W2 = (const float*)d_in[10];
    const float* b2 = (const float*)d_in[11];
    const float* g2 = (const float*)d_in[12];
    const float* be2= (const float*)d_in[13];
    const float* m2 = (const float*)d_in[14];
    const float* v2 = (const float*)d_in[15];
    float* out = (float*)d_out;

    float* feats1_ptr = nullptr;
    int*   idx_ptr    = nullptr;
    float* w_ptr      = nullptr;
    __nv_bfloat16 *p1h, *p1l, *p2h, *p2l, *w1h, *w1l, *w2h, *w2l;
    cudaGetSymbolAddress((void**)&feats1_ptr, g_feats1);
    cudaGetSymbolAddress((void**)&idx_ptr,    g_idx);
    cudaGetSymbolAddress((void**)&w_ptr,      g_w);
    cudaGetSymbolAddress((void**)&p1h, g_p1h);
    cudaGetSymbolAddress((void**)&p1l, g_p1l);
    cudaGetSymbolAddress((void**)&p2h, g_p2h);
    cudaGetSymbolAddress((void**)&p2l, g_p2l);
    cudaGetSymbolAddress((void**)&w1h, g_w1h);
    cudaGetSymbolAddress((void**)&w1l, g_w1l);
    cudaGetSymbolAddress((void**)&w2h, g_w2h);
    cudaGetSymbolAddress((void**)&w2l, g_w2l);

    static int attr_set = 0;
    if (!attr_set) {
        cudaFuncSetAttribute(knn3_kernel,
                             cudaFuncAttributeMaxDynamicSharedMemorySize,
                             N1 * (int)sizeof(float4));
        cudaFuncSetAttribute(gemm_mma_bn_relu,
                             cudaFuncAttributeMaxDynamicSharedMemorySize,
                             GSM_TOTAL);
        attr_set = 1;
    }

    // fp32 -> bf16 hi/lo pre-splits (memory-bound)
    {
        int n4;
        n4 = BB * N1 * DIM1 / 4;
        split_bf16_kernel<<<(n4 + 255) / 256, 256>>>(points1, p1h, p1l, n4);
        n4 = BB * N2 * DIM2 / 4;
        split_bf16_kernel<<<(n4 + 255) / 256, 256>>>(points2, p2h, p2l, n4);
        n4 = DOUT * DIM1 / 4;
        split_bf16_kernel<<<(n4 + 255) / 256, 256>>>(W1, w1h, w1l, n4);
        n4 = DOUT * DIM2 / 4;
        split_bf16_kernel<<<(n4 + 255) / 256, 256>>>(W2, w2h, w2l, n4);
    }

    // KNN
    knn3_kernel<<<dim3(N2 / 256, BB), 256, N1 * sizeof(float4)>>>(
        xyz2, xyz1, idx_ptr, w_ptr);

    // feats1 = relu(BN(points1 @ W1^T + b1)) -> scratch
    gemm_mma_bn_relu<<<dim3((BB * N1) / 64, 2), 128, GSM_TOTAL>>>(
        p1h, p1l, w1h, w1l, b1, g1, be1, m1, v1,
        feats1_ptr, DIM1, nullptr, nullptr, nullptr);

    // out = relu(BN(points2 @ W2^T + b2)) + interp(feats1)   [fused]
    gemm_mma_bn_relu<<<dim3((BB * N2) / 64, 2), 128, GSM_TOTAL>>>(
        p2h, p2l, w2h, w2l, b2, g2, be2, m2, v2,
        out, DIM2, feats1_ptr, idx_ptr, w_ptr);
}